// round 3
// baseline (speedup 1.0000x reference)
#include <cuda_runtime.h>
#include <cstdint>

// Problem constants (fixed shapes from setup_inputs)
static constexpr int B_    = 8;
static constexpr int C_    = 256;
static constexpr int N_    = 1024;   // T*H*W
static constexpr int HEADS = 8;
static constexpr int DK    = 1024;   // KC / heads
static constexpr int DV    = 64;     // VC / heads
static constexpr int KC    = 8192;
static constexpr int VC    = 512;
static constexpr int CHUNKSZ = 128;
static constexpr int NCHUNK  = 8;

// Device scratch (no cudaMalloc allowed)
__device__ float g_A [(size_t)B_ * HEADS * C_ * C_];    // [b,h][256][256]   16 MB
__device__ float g_P [(size_t)B_ * HEADS * DK * C_];    // [b,h][1024][256]  64 MB
__device__ float g_v [(size_t)B_ * VC * N_];            // [b][512][1024]    16 MB
__device__ float g_o2[(size_t)B_ * VC * N_];            // [b][512][1024]    16 MB

// ---------------------------------------------------------------------------
// Packed f32x2 helpers (sm_103a FFMA2 path — only reachable via PTX)
// ---------------------------------------------------------------------------
__device__ __forceinline__ void fma2(unsigned long long& d,
                                     unsigned long long a,
                                     unsigned long long b)
{
    asm("fma.rn.f32x2 %0, %1, %2, %0;" : "+l"(d) : "l"(a), "l"(b));
}

__device__ __forceinline__ unsigned long long pack2(float v)
{
    unsigned long long r;
    unsigned u = __float_as_uint(v);
    asm("mov.b64 %0, {%1, %1};" : "=l"(r) : "r"(u));
    return r;
}

__device__ __forceinline__ float2 unpack2(unsigned long long v)
{
    float2 f;
    asm("mov.b64 {%0, %1}, %2;" : "=f"(f.x), "=f"(f.y) : "l"(v));
    return f;
}

// A-operand smem stride (duplicated pairs): 256 payload + 12 pad floats.
// 268*4 = 1072 bytes, 16B-aligned per row (LDS.128 safe).
static constexpr int WS2_STRIDE = 268;

// ---------------------------------------------------------------------------
// Generalized batched SGEMM: Out[z] (MxN) = W[z] (MxK) @ X[z] (KxN) [+ bias]
// BM=BN=128, BK=16, 256 threads, 8x8 per-thread micro-tile, FFMA2 inner loop.
// Requires M%128==0, N%128==0, K%16==0.
// ---------------------------------------------------------------------------
__global__ __launch_bounds__(256, 2)
void sgemm2_kernel(const float* __restrict__ W, const float* __restrict__ X,
                   float* __restrict__ Out, const float* __restrict__ bias,
                   int M, int K, int N, int hbits,
                   long long sWb, long long sWh,
                   long long sXb, long long sXh,
                   long long sOb, long long sOh)
{
    __shared__ float Ws2[16 * WS2_STRIDE];   // duplicated (a,a) pairs
    __shared__ float Xs[16 * 132];

    const int z = blockIdx.z;
    const int b = z >> hbits;
    const int h = z & ((1 << hbits) - 1);
    const float* Wp = W + (size_t)b * sWb + (size_t)h * sWh;
    const float* Xp = X + (size_t)b * sXb + (size_t)h * sXh;
    float*       Op = Out + (size_t)b * sOb + (size_t)h * sOh;

    const int m0 = blockIdx.y * 128;
    const int n0 = blockIdx.x * 128;
    const int tid = threadIdx.x;
    const int tx = tid & 15;
    const int ty = tid >> 4;

    unsigned long long acc2[8][4];
#pragma unroll
    for (int i = 0; i < 8; ++i)
#pragma unroll
        for (int j = 0; j < 4; ++j) acc2[i][j] = 0ull;

    for (int k0 = 0; k0 < K; k0 += 16) {
        // W tile [128 m][16 k] -> Ws2[k][2m],[2m+1] duplicated
#pragma unroll
        for (int it = 0; it < 2; ++it) {
            int idx = it * 256 + tid;
            int m   = idx >> 2;
            int kq  = (idx & 3) * 4;
            float4 w4 = *reinterpret_cast<const float4*>(Wp + (size_t)(m0 + m) * K + k0 + kq);
            float2 d;
            d.x = d.y = w4.x; *reinterpret_cast<float2*>(&Ws2[(kq + 0) * WS2_STRIDE + 2 * m]) = d;
            d.x = d.y = w4.y; *reinterpret_cast<float2*>(&Ws2[(kq + 1) * WS2_STRIDE + 2 * m]) = d;
            d.x = d.y = w4.z; *reinterpret_cast<float2*>(&Ws2[(kq + 2) * WS2_STRIDE + 2 * m]) = d;
            d.x = d.y = w4.w; *reinterpret_cast<float2*>(&Ws2[(kq + 3) * WS2_STRIDE + 2 * m]) = d;
        }
        // X tile [16 k][128 n] direct
#pragma unroll
        for (int it = 0; it < 2; ++it) {
            int idx = it * 256 + tid;
            int kk  = idx >> 5;
            int nq  = (idx & 31) * 4;
            *reinterpret_cast<float4*>(&Xs[kk * 132 + nq]) =
                *reinterpret_cast<const float4*>(Xp + (size_t)(k0 + kk) * N + n0 + nq);
        }
        __syncthreads();

#pragma unroll
        for (int kk = 0; kk < 16; ++kk) {
            const float* wrow = &Ws2[kk * WS2_STRIDE + ty * 16];
            ulonglong2 a01 = *reinterpret_cast<const ulonglong2*>(wrow + 0);
            ulonglong2 a23 = *reinterpret_cast<const ulonglong2*>(wrow + 4);
            ulonglong2 a45 = *reinterpret_cast<const ulonglong2*>(wrow + 8);
            ulonglong2 a67 = *reinterpret_cast<const ulonglong2*>(wrow + 12);
            const float* xrow = &Xs[kk * 132 + tx * 8];
            ulonglong2 b01 = *reinterpret_cast<const ulonglong2*>(xrow + 0);
            ulonglong2 b23 = *reinterpret_cast<const ulonglong2*>(xrow + 4);
            unsigned long long a[8] = {a01.x, a01.y, a23.x, a23.y, a45.x, a45.y, a67.x, a67.y};
            unsigned long long bb[4] = {b01.x, b01.y, b23.x, b23.y};
#pragma unroll
            for (int i = 0; i < 8; ++i)
#pragma unroll
                for (int j = 0; j < 4; ++j)
                    fma2(acc2[i][j], a[i], bb[j]);
        }
        __syncthreads();
    }

#pragma unroll
    for (int i = 0; i < 8; ++i) {
        int m = m0 + ty * 8 + i;
        float bv = bias ? bias[m] : 0.f;
#pragma unroll
        for (int j = 0; j < 4; j += 2) {
            float2 lo = unpack2(acc2[i][j]);
            float2 hi = unpack2(acc2[i][j + 1]);
            float4 o;
            o.x = lo.x + bv; o.y = lo.y + bv;
            o.z = hi.x + bv; o.w = hi.y + bv;
            *reinterpret_cast<float4*>(Op + (size_t)m * N + n0 + tx * 8 + 2 * j) = o;
        }
    }
}

// ---------------------------------------------------------------------------
// Fused attention kernel: one CTA per (chunk, head, batch).
// Phase A: S[128,128] = P[i-tile,:256] @ x_b[:256, chunk]  (FFMA2)
// softmax per row over the 128 chunk columns
// Phase B: O[64,128] += V[:, i-tile] @ attn[128,128]       (FFMA2)
// ---------------------------------------------------------------------------
__global__ __launch_bounds__(256, 1)
void attn_kernel(const float* __restrict__ x)
{
    extern __shared__ float sm[];
    float* Ks2 = sm;                            // [16][268] duplicated pairs
    float* Qs  = sm + 16 * WS2_STRIDE;          // [16][132]
    float* Sa  = Qs + 16 * 132;                 // [128][132]
    float* Vs  = Sa + 128 * 132;                // [64][132]

    const int chunk = blockIdx.x;
    const int h     = blockIdx.y;
    const int b     = blockIdx.z;

    const float* Pp = g_P + (size_t)(b * HEADS + h) * DK * C_;   // [1024 i][256 c]
    const float* Xp = x + (size_t)b * C_ * N_;                   // [256 c][1024 j]
    const float* Vp = g_v + ((size_t)b * VC + h * DV) * N_;      // [64 d][1024 i]
    float*       Op = g_o2 + ((size_t)b * VC + h * DV) * N_ + chunk * CHUNKSZ;

    const int j0 = chunk * CHUNKSZ;
    const int tid = threadIdx.x;
    const int tx = tid & 15;
    const int ty = tid >> 4;

    const float scale = 0.03125f;  // 1/sqrt(1024)

    unsigned long long Oacc2[4][4];
#pragma unroll
    for (int d = 0; d < 4; ++d)
#pragma unroll
        for (int c = 0; c < 4; ++c) Oacc2[d][c] = 0ull;

    for (int it = 0; it < 8; ++it) {
        const int i0 = it * 128;

        // ---------- Phase A: scores tile, K = 256 ----------
        unsigned long long S2[8][4];
#pragma unroll
        for (int r = 0; r < 8; ++r)
#pragma unroll
            for (int c = 0; c < 4; ++c) S2[r][c] = 0ull;

        for (int m0 = 0; m0 < C_; m0 += 16) {
            // P tile [128 i][16 c] -> Ks2[c][2i],[2i+1] duplicated
#pragma unroll
            for (int itr = 0; itr < 2; ++itr) {
                int idx = itr * 256 + tid;
                int i   = idx >> 2;
                int mq  = (idx & 3) * 4;
                float4 k4 = *reinterpret_cast<const float4*>(Pp + (size_t)(i0 + i) * C_ + m0 + mq);
                float2 d;
                d.x = d.y = k4.x; *reinterpret_cast<float2*>(&Ks2[(mq + 0) * WS2_STRIDE + 2 * i]) = d;
                d.x = d.y = k4.y; *reinterpret_cast<float2*>(&Ks2[(mq + 1) * WS2_STRIDE + 2 * i]) = d;
                d.x = d.y = k4.z; *reinterpret_cast<float2*>(&Ks2[(mq + 2) * WS2_STRIDE + 2 * i]) = d;
                d.x = d.y = k4.w; *reinterpret_cast<float2*>(&Ks2[(mq + 3) * WS2_STRIDE + 2 * i]) = d;
            }
            // x tile [16 c][128 j] direct
#pragma unroll
            for (int itr = 0; itr < 2; ++itr) {
                int idx = itr * 256 + tid;
                int kk  = idx >> 5;
                int nq  = (idx & 31) * 4;
                *reinterpret_cast<float4*>(&Qs[kk * 132 + nq]) =
                    *reinterpret_cast<const float4*>(Xp + (size_t)(m0 + kk) * N_ + j0 + nq);
            }
            __syncthreads();

#pragma unroll
            for (int kk = 0; kk < 16; ++kk) {
                const float* krow = &Ks2[kk * WS2_STRIDE + ty * 16];
                ulonglong2 a01 = *reinterpret_cast<const ulonglong2*>(krow + 0);
                ulonglong2 a23 = *reinterpret_cast<const ulonglong2*>(krow + 4);
                ulonglong2 a45 = *reinterpret_cast<const ulonglong2*>(krow + 8);
                ulonglong2 a67 = *reinterpret_cast<const ulonglong2*>(krow + 12);
                const float* qrow = &Qs[kk * 132 + tx * 8];
                ulonglong2 b01 = *reinterpret_cast<const ulonglong2*>(qrow + 0);
                ulonglong2 b23 = *reinterpret_cast<const ulonglong2*>(qrow + 4);
                unsigned long long a[8] = {a01.x, a01.y, a23.x, a23.y, a45.x, a45.y, a67.x, a67.y};
                unsigned long long bb[4] = {b01.x, b01.y, b23.x, b23.y};
#pragma unroll
                for (int r = 0; r < 8; ++r)
#pragma unroll
                    for (int c = 0; c < 4; ++c)
                        fma2(S2[r][c], a[r], bb[c]);
            }
            __syncthreads();
        }

        // ---------- Softmax per row over the 128 chunk columns ----------
        float S[8][8];
#pragma unroll
        for (int r = 0; r < 8; ++r)
#pragma unroll
            for (int c = 0; c < 4; ++c) {
                float2 f = unpack2(S2[r][c]);
                S[r][2 * c] = f.x; S[r][2 * c + 1] = f.y;
            }

#pragma unroll
        for (int r = 0; r < 8; ++r) {
            float mx = -1e30f;
#pragma unroll
            for (int c = 0; c < 8; ++c) { S[r][c] *= scale; mx = fmaxf(mx, S[r][c]); }
#pragma unroll
            for (int off = 8; off >= 1; off >>= 1)
                mx = fmaxf(mx, __shfl_xor_sync(0xffffffffu, mx, off));
            float sum = 0.f;
#pragma unroll
            for (int c = 0; c < 8; ++c) { S[r][c] = __expf(S[r][c] - mx); sum += S[r][c]; }
#pragma unroll
            for (int off = 8; off >= 1; off >>= 1)
                sum += __shfl_xor_sync(0xffffffffu, sum, off);
            float inv = 1.0f / sum;
#pragma unroll
            for (int c = 0; c < 8; ++c) S[r][c] *= inv;
        }

        // ---------- Stage attn to smem + load V tile ----------
#pragma unroll
        for (int r = 0; r < 8; ++r)
#pragma unroll
            for (int c = 0; c < 8; c += 4) {
                float4 o;
                o.x = S[r][c + 0]; o.y = S[r][c + 1]; o.z = S[r][c + 2]; o.w = S[r][c + 3];
                *reinterpret_cast<float4*>(&Sa[(ty * 8 + r) * 132 + tx * 8 + c]) = o;
            }
#pragma unroll
        for (int itr = 0; itr < 8; ++itr) {
            int idx = itr * 256 + tid;
            int d   = idx >> 5;
            int cq  = (idx & 31) * 4;
            *reinterpret_cast<float4*>(&Vs[d * 132 + cq]) =
                *reinterpret_cast<const float4*>(Vp + (size_t)d * N_ + i0 + cq);
        }
        __syncthreads();

        // ---------- Phase B: O += V_tile @ attn ----------
#pragma unroll 4
        for (int kk = 0; kk < 128; ++kk) {
            const float* srow = &Sa[kk * 132 + tx * 8];
            ulonglong2 b01 = *reinterpret_cast<const ulonglong2*>(srow + 0);
            ulonglong2 b23 = *reinterpret_cast<const ulonglong2*>(srow + 4);
            unsigned long long bb[4] = {b01.x, b01.y, b23.x, b23.y};
#pragma unroll
            for (int dd = 0; dd < 4; ++dd) {
                unsigned long long av = pack2(Vs[(ty * 4 + dd) * 132 + kk]);
#pragma unroll
                for (int c = 0; c < 4; ++c)
                    fma2(Oacc2[dd][c], av, bb[c]);
            }
        }
        __syncthreads();
    }

    // write O tile [64 d][128 j]
#pragma unroll
    for (int dd = 0; dd < 4; ++dd)
#pragma unroll
        for (int c = 0; c < 4; c += 2) {
            float2 lo = unpack2(Oacc2[dd][c]);
            float2 hi = unpack2(Oacc2[dd][c + 1]);
            float4 o;
            o.x = lo.x; o.y = lo.y; o.z = hi.x; o.w = hi.y;
            *reinterpret_cast<float4*>(Op + (size_t)(ty * 4 + dd) * N_ + tx * 8 + 2 * c) = o;
        }
}

// ---------------------------------------------------------------------------
// Launch
// ---------------------------------------------------------------------------
extern "C" void kernel_launch(void* const* d_in, const int* in_sizes, int n_in,
                              void* d_out, int out_size)
{
    const float* x  = (const float*)d_in[0];
    const float* Wk = (const float*)d_in[1];
    const float* Wq = (const float*)d_in[2];
    const float* Wv = (const float*)d_in[3];
    const float* Wr = (const float*)d_in[4];
    const float* br = (const float*)d_in[5];
    float* out = (float*)d_out;

    float *gA, *gP, *gv, *go2;
    cudaGetSymbolAddress((void**)&gA,  g_A);
    cudaGetSymbolAddress((void**)&gP,  g_P);
    cudaGetSymbolAddress((void**)&gv,  g_v);
    cudaGetSymbolAddress((void**)&go2, g_o2);

    dim3 blk(256);

    // A[b,h] = x_b (256x1024) @ Wq_h (1024x256)
    sgemm2_kernel<<<dim3(C_ / 128, C_ / 128, B_ * HEADS), blk>>>(
        x, Wq, gA, nullptr,
        C_, N_, C_, 3,
        (long long)C_ * N_, 0,
        0, (long long)DK * C_,
        (long long)HEADS * C_ * C_, (long long)C_ * C_);

    // P[b,h] = Wk_h (1024x256) @ A[b,h] (256x256)
    sgemm2_kernel<<<dim3(C_ / 128, DK / 128, B_ * HEADS), blk>>>(
        Wk, gA, gP, nullptr,
        DK, C_, C_, 3,
        0, (long long)DK * C_,
        (long long)HEADS * C_ * C_, (long long)C_ * C_,
        (long long)HEADS * DK * C_, (long long)DK * C_);

    // v = Wv @ x_b : [B][512][1024]
    sgemm2_kernel<<<dim3(N_ / 128, VC / 128, B_), blk>>>(
        Wv, x, gv, nullptr,
        VC, C_, N_, 0,
        0, 0,
        (long long)C_ * N_, 0,
        (long long)VC * N_, 0);

    // fused scores(K=256) -> chunked softmax -> V @ attn
    const int smem_bytes = (16 * WS2_STRIDE + 16 * 132 + 128 * 132 + 64 * 132) * (int)sizeof(float);
    cudaFuncSetAttribute(attn_kernel, cudaFuncAttributeMaxDynamicSharedMemorySize, smem_bytes);
    attn_kernel<<<dim3(NCHUNK, HEADS, B_), blk, smem_bytes>>>(x);

    // y = Wr @ o2 + br : [B][256][1024]
    sgemm2_kernel<<<dim3(N_ / 128, C_ / 128, B_), blk>>>(
        Wr, go2, out, br,
        C_, VC, N_, 0,
        0, 0,
        (long long)VC * N_, 0,
        (long long)C_ * N_, 0);
}

// round 4
// speedup vs baseline: 2.0260x; 2.0260x over previous
#include <cuda_runtime.h>
#include <cuda_bf16.h>
#include <cstdint>

// Problem constants (fixed shapes from setup_inputs)
static constexpr int B_    = 8;
static constexpr int C_    = 256;
static constexpr int N_    = 1024;   // T*H*W
static constexpr int HEADS = 8;
static constexpr int DK    = 1024;   // KC / heads
static constexpr int DV    = 64;     // VC / heads
static constexpr int KC    = 8192;
static constexpr int VC    = 512;
static constexpr int CHUNKSZ = 128;
static constexpr int NCHUNK  = 8;

// Device scratch (no cudaMalloc allowed)
__device__ float g_A [(size_t)B_ * HEADS * C_ * C_];    // [b,h][256][256]
__device__ float g_P [(size_t)B_ * HEADS * DK * C_];    // [b,h][1024][256]
__device__ float g_v [(size_t)B_ * VC * N_];            // [b][512][1024]
__device__ float g_o2[(size_t)B_ * VC * N_];            // [b][512][1024]

// ---------------------------------------------------------------------------
// Helpers: bf16 split + packing + warp MMA
// ---------------------------------------------------------------------------
__device__ __forceinline__ float bf16hi(float f)
{
    return __bfloat162float(__float2bfloat16(f));
}

// pack two floats (rounded to bf16) into one u32: lo_el -> low half
__device__ __forceinline__ uint32_t packbf(float lo_el, float hi_el)
{
    uint32_t r;
    asm("cvt.rn.bf16x2.f32 %0, %1, %2;" : "=r"(r) : "f"(hi_el), "f"(lo_el));
    return r;
}

__device__ __forceinline__ void mma16816(float* d, const uint32_t* a, const uint32_t* b)
{
    asm volatile(
        "mma.sync.aligned.m16n8k16.row.col.f32.bf16.bf16.f32 "
        "{%0,%1,%2,%3}, {%4,%5,%6,%7}, {%8,%9}, {%0,%1,%2,%3};"
        : "+f"(d[0]), "+f"(d[1]), "+f"(d[2]), "+f"(d[3])
        : "r"(a[0]), "r"(a[1]), "r"(a[2]), "r"(a[3]), "r"(b[0]), "r"(b[1]));
}

// smem strides in u32 words (bf16 pairs along k)
static constexpr int SW  = 20;  // 40 bf16 per row (32 payload + 8 pad)
static constexpr int SWP = 69;  // Pa stride: 138 bf16 (128 payload)
static constexpr int SWV = 68;  // V stride: 136 bf16 (128 payload)

// ---------------------------------------------------------------------------
// Generic batched GEMM via bf16x3-split tensor-core MMA.
// Out[z] (MxN) = W[z] (MxK) @ X[z] (KxN) [+ bias], fp32 in/out.
// CTA tile 128x128, K-stage 32, 256 threads = 8 warps (2m x 4n), warp 64x32.
// Requires M%128==0, N%128==0, K%32==0.
// ---------------------------------------------------------------------------
__global__ __launch_bounds__(256, 2)
void mgemm_kernel(const float* __restrict__ W, const float* __restrict__ X,
                  float* __restrict__ Out, const float* __restrict__ bias,
                  int M, int K, int N, int hbits,
                  long long sWb, long long sWh,
                  long long sXb, long long sXh,
                  long long sOb, long long sOh)
{
    __shared__ uint32_t Whi[128 * SW], Wlo[128 * SW];
    __shared__ uint32_t Xhi[128 * SW], Xlo[128 * SW];

    const int z = blockIdx.z;
    const int zb = z >> hbits;
    const int zh = z & ((1 << hbits) - 1);
    const float* Wp = W + (size_t)zb * sWb + (size_t)zh * sWh;
    const float* Xp = X + (size_t)zb * sXb + (size_t)zh * sXh;
    float*       Op = Out + (size_t)zb * sOb + (size_t)zh * sOh;

    const int m0 = blockIdx.y * 128;
    const int n0 = blockIdx.x * 128;
    const int tid  = threadIdx.x;
    const int lane = tid & 31;
    const int wid  = tid >> 5;
    const int wm = wid >> 2;      // 0..1
    const int wn = wid & 3;       // 0..3
    const int g  = lane >> 2;     // 0..7
    const int cc = lane & 3;      // 0..3

    float acc[4][4][4];
#pragma unroll
    for (int mt = 0; mt < 4; ++mt)
#pragma unroll
        for (int nt = 0; nt < 4; ++nt)
#pragma unroll
            for (int e = 0; e < 4; ++e) acc[mt][nt][e] = 0.f;

    for (int k0 = 0; k0 < K; k0 += 32) {
        // ---- stage W tile [128 m][32 k] -> hi/lo bf16 (k contiguous) ----
        {
            const int r = tid >> 1;
            const int half = tid & 1;
            const float* src = Wp + (size_t)(m0 + r) * K + k0 + half * 16;
#pragma unroll
            for (int q = 0; q < 4; ++q) {
                float4 f = *reinterpret_cast<const float4*>(src + q * 4);
                float h0 = bf16hi(f.x), h1 = bf16hi(f.y), h2 = bf16hi(f.z), h3 = bf16hi(f.w);
                int w = r * SW + half * 8 + q * 2;
                Whi[w]     = packbf(h0, h1);
                Whi[w + 1] = packbf(h2, h3);
                Wlo[w]     = packbf(f.x - h0, f.y - h1);
                Wlo[w + 1] = packbf(f.z - h2, f.w - h3);
            }
        }
        // ---- stage X tile [32 k][128 n] -> transposed [n][k] hi/lo ----
        {
            const int n = tid & 127;
            const int kh = tid >> 7;   // 0..1
            const float* src = Xp + (size_t)(k0 + kh * 16) * N + n0 + n;
#pragma unroll
            for (int kq = 0; kq < 8; ++kq) {
                float f0 = src[(size_t)(2 * kq) * N];
                float f1 = src[(size_t)(2 * kq + 1) * N];
                float h0 = bf16hi(f0), h1 = bf16hi(f1);
                int w = n * SW + kh * 8 + kq;
                Xhi[w] = packbf(h0, h1);
                Xlo[w] = packbf(f0 - h0, f1 - h1);
            }
        }
        __syncthreads();

#pragma unroll
        for (int h16 = 0; h16 < 2; ++h16) {
            const int ko = h16 * 8;
            uint32_t bhi[4][2], blo[4][2];
#pragma unroll
            for (int nt = 0; nt < 4; ++nt) {
                int col = (wn * 32 + nt * 8 + g) * SW;
                bhi[nt][0] = Xhi[col + ko + cc];
                bhi[nt][1] = Xhi[col + ko + 4 + cc];
                blo[nt][0] = Xlo[col + ko + cc];
                blo[nt][1] = Xlo[col + ko + 4 + cc];
            }
#pragma unroll
            for (int mt = 0; mt < 4; ++mt) {
                int r0 = (wm * 64 + mt * 16 + g) * SW;
                int r8 = r0 + 8 * SW;
                uint32_t ahi[4] = { Whi[r0 + ko + cc], Whi[r8 + ko + cc],
                                    Whi[r0 + ko + 4 + cc], Whi[r8 + ko + 4 + cc] };
                uint32_t alo[4] = { Wlo[r0 + ko + cc], Wlo[r8 + ko + cc],
                                    Wlo[r0 + ko + 4 + cc], Wlo[r8 + ko + 4 + cc] };
#pragma unroll
                for (int nt = 0; nt < 4; ++nt) {
                    mma16816(acc[mt][nt], ahi, bhi[nt]);
                    mma16816(acc[mt][nt], ahi, blo[nt]);
                    mma16816(acc[mt][nt], alo, bhi[nt]);
                }
            }
        }
        __syncthreads();
    }

    // ---- epilogue ----
#pragma unroll
    for (int mt = 0; mt < 4; ++mt) {
#pragma unroll
        for (int nt = 0; nt < 4; ++nt) {
            int row = m0 + wm * 64 + mt * 16 + g;
            int col = n0 + wn * 32 + nt * 8 + 2 * cc;
            float b0 = bias ? bias[row] : 0.f;
            float b1 = bias ? bias[row + 8] : 0.f;
            float2 v;
            v.x = acc[mt][nt][0] + b0; v.y = acc[mt][nt][1] + b0;
            *reinterpret_cast<float2*>(Op + (size_t)row * N + col) = v;
            v.x = acc[mt][nt][2] + b1; v.y = acc[mt][nt][3] + b1;
            *reinterpret_cast<float2*>(Op + (size_t)(row + 8) * N + col) = v;
        }
    }
}

// ---------------------------------------------------------------------------
// Fused attention kernel (tensor-core version).
// One CTA per (chunk, head, batch). For each of 8 i-tiles (128 rows of dk):
//   Phase A: S[128,128] = P[i-tile,:256] @ x_b[:256, chunk]  (bf16x3 MMA)
//   softmax over the 128 chunk columns (fp32, from smem)
//   Phase B: O[64,128] += V[:, i-tile] @ attn                (bf16x3 MMA)
// ---------------------------------------------------------------------------
__global__ __launch_bounds__(256, 1)
void attn_kernel(const float* __restrict__ x)
{
    extern __shared__ __align__(16) char smraw[];
    uint32_t* Phi  = reinterpret_cast<uint32_t*>(smraw);           // 128*SW
    uint32_t* Plo  = Phi  + 128 * SW;
    uint32_t* Xqhi = Plo  + 128 * SW;
    uint32_t* Xqlo = Xqhi + 128 * SW;
    float*    Sa   = reinterpret_cast<float*>(Xqlo + 128 * SW);    // [128][132] fp32
    uint32_t* Pahi = reinterpret_cast<uint32_t*>(Sa + 128 * 132);  // [128 j][SWP]
    uint32_t* Palo = Pahi + 128 * SWP;
    uint32_t* Vhi  = Palo + 128 * SWP;                             // [64 d][SWV]
    uint32_t* Vlo  = Vhi  + 64 * SWV;

    const int chunk = blockIdx.x;
    const int h     = blockIdx.y;
    const int b     = blockIdx.z;

    const float* Pp = g_P + (size_t)(b * HEADS + h) * DK * C_;   // [1024 i][256 c]
    const float* Xp = x + (size_t)b * C_ * N_;                   // [256 c][1024 j]
    const float* Vp = g_v + ((size_t)b * VC + h * DV) * N_;      // [64 d][1024 i]
    float*       Op = g_o2 + ((size_t)b * VC + h * DV) * N_ + chunk * CHUNKSZ;

    const int j0 = chunk * CHUNKSZ;
    const int tid  = threadIdx.x;
    const int lane = tid & 31;
    const int wid  = tid >> 5;
    const int wm = wid >> 2;
    const int wn = wid & 3;
    const int g  = lane >> 2;
    const int cc = lane & 3;
    const int tx = tid & 15;
    const int ty = tid >> 4;

    const float scale = 0.03125f;  // 1/sqrt(1024)

    float oacc[2][4][4];
#pragma unroll
    for (int mt = 0; mt < 2; ++mt)
#pragma unroll
        for (int nt = 0; nt < 4; ++nt)
#pragma unroll
            for (int e = 0; e < 4; ++e) oacc[mt][nt][e] = 0.f;

    for (int it = 0; it < 8; ++it) {
        const int i0 = it * 128;

        // ================= Phase A: S = P_tile @ x_chunk (K=256) ===========
        float sacc[4][4][4];
#pragma unroll
        for (int mt = 0; mt < 4; ++mt)
#pragma unroll
            for (int nt = 0; nt < 4; ++nt)
#pragma unroll
                for (int e = 0; e < 4; ++e) sacc[mt][nt][e] = 0.f;

        for (int m0 = 0; m0 < C_; m0 += 32) {
            // stage P tile [128 i][32 c]
            {
                const int r = tid >> 1;
                const int half = tid & 1;
                const float* src = Pp + (size_t)(i0 + r) * C_ + m0 + half * 16;
#pragma unroll
                for (int q = 0; q < 4; ++q) {
                    float4 f = *reinterpret_cast<const float4*>(src + q * 4);
                    float h0 = bf16hi(f.x), h1 = bf16hi(f.y), h2 = bf16hi(f.z), h3 = bf16hi(f.w);
                    int w = r * SW + half * 8 + q * 2;
                    Phi[w]     = packbf(h0, h1);
                    Phi[w + 1] = packbf(h2, h3);
                    Plo[w]     = packbf(f.x - h0, f.y - h1);
                    Plo[w + 1] = packbf(f.z - h2, f.w - h3);
                }
            }
            // stage x tile [32 c][128 j] -> [j][c]
            {
                const int n = tid & 127;
                const int kh = tid >> 7;
                const float* src = Xp + (size_t)(m0 + kh * 16) * N_ + j0 + n;
#pragma unroll
                for (int kq = 0; kq < 8; ++kq) {
                    float f0 = src[(size_t)(2 * kq) * N_];
                    float f1 = src[(size_t)(2 * kq + 1) * N_];
                    float h0 = bf16hi(f0), h1 = bf16hi(f1);
                    int w = n * SW + kh * 8 + kq;
                    Xqhi[w] = packbf(h0, h1);
                    Xqlo[w] = packbf(f0 - h0, f1 - h1);
                }
            }
            __syncthreads();

#pragma unroll
            for (int h16 = 0; h16 < 2; ++h16) {
                const int ko = h16 * 8;
                uint32_t bhi[4][2], blo[4][2];
#pragma unroll
                for (int nt = 0; nt < 4; ++nt) {
                    int col = (wn * 32 + nt * 8 + g) * SW;
                    bhi[nt][0] = Xqhi[col + ko + cc];
                    bhi[nt][1] = Xqhi[col + ko + 4 + cc];
                    blo[nt][0] = Xqlo[col + ko + cc];
                    blo[nt][1] = Xqlo[col + ko + 4 + cc];
                }
#pragma unroll
                for (int mt = 0; mt < 4; ++mt) {
                    int r0 = (wm * 64 + mt * 16 + g) * SW;
                    int r8 = r0 + 8 * SW;
                    uint32_t ahi[4] = { Phi[r0 + ko + cc], Phi[r8 + ko + cc],
                                        Phi[r0 + ko + 4 + cc], Phi[r8 + ko + 4 + cc] };
                    uint32_t alo[4] = { Plo[r0 + ko + cc], Plo[r8 + ko + cc],
                                        Plo[r0 + ko + 4 + cc], Plo[r8 + ko + 4 + cc] };
#pragma unroll
                    for (int nt = 0; nt < 4; ++nt) {
                        mma16816(sacc[mt][nt], ahi, bhi[nt]);
                        mma16816(sacc[mt][nt], ahi, blo[nt]);
                        mma16816(sacc[mt][nt], alo, bhi[nt]);
                    }
                }
            }
            __syncthreads();
        }

        // ---- write S fragments to Sa (fp32) ----
#pragma unroll
        for (int mt = 0; mt < 4; ++mt)
#pragma unroll
            for (int nt = 0; nt < 4; ++nt) {
                int row = wm * 64 + mt * 16 + g;
                int col = wn * 32 + nt * 8 + 2 * cc;
                float2 v;
                v.x = sacc[mt][nt][0]; v.y = sacc[mt][nt][1];
                *reinterpret_cast<float2*>(&Sa[row * 132 + col]) = v;
                v.x = sacc[mt][nt][2]; v.y = sacc[mt][nt][3];
                *reinterpret_cast<float2*>(&Sa[(row + 8) * 132 + col]) = v;
            }
        __syncthreads();

        // ================= Softmax over 128 chunk columns ===================
        {
            float P_[8][8];
#pragma unroll
            for (int r = 0; r < 8; ++r) {
                float4 a4 = *reinterpret_cast<const float4*>(&Sa[(ty * 8 + r) * 132 + tx * 8]);
                float4 b4 = *reinterpret_cast<const float4*>(&Sa[(ty * 8 + r) * 132 + tx * 8 + 4]);
                P_[r][0] = a4.x; P_[r][1] = a4.y; P_[r][2] = a4.z; P_[r][3] = a4.w;
                P_[r][4] = b4.x; P_[r][5] = b4.y; P_[r][6] = b4.z; P_[r][7] = b4.w;
            }
#pragma unroll
            for (int r = 0; r < 8; ++r) {
                float mx = -1e30f;
#pragma unroll
                for (int c = 0; c < 8; ++c) { P_[r][c] *= scale; mx = fmaxf(mx, P_[r][c]); }
#pragma unroll
                for (int off = 8; off >= 1; off >>= 1)
                    mx = fmaxf(mx, __shfl_xor_sync(0xffffffffu, mx, off));
                float sum = 0.f;
#pragma unroll
                for (int c = 0; c < 8; ++c) { P_[r][c] = __expf(P_[r][c] - mx); sum += P_[r][c]; }
#pragma unroll
                for (int off = 8; off >= 1; off >>= 1)
                    sum += __shfl_xor_sync(0xffffffffu, sum, off);
                float inv = 1.0f / sum;
#pragma unroll
                for (int c = 0; c < 8; ++c) P_[r][c] *= inv;
            }
            // write attn transposed [j][i] as bf16 hi/lo (i-pairs packed)
#pragma unroll
            for (int c = 0; c < 8; ++c) {
                int base = (tx * 8 + c) * SWP + ty * 4;
#pragma unroll
                for (int s = 0; s < 4; ++s) {
                    float p0 = P_[2 * s][c], p1 = P_[2 * s + 1][c];
                    float h0 = bf16hi(p0), h1 = bf16hi(p1);
                    Pahi[base + s] = packbf(h0, h1);
                    Palo[base + s] = packbf(p0 - h0, p1 - h1);
                }
            }
        }
        // ---- stage V tile [64 d][128 i] hi/lo ----
        {
            const int d0 = tid >> 5;       // 0..7
            const int iw = lane * 4;       // 0..124
#pragma unroll
            for (int dd = 0; dd < 8; ++dd) {
                int d = d0 + dd * 8;
                float4 f = *reinterpret_cast<const float4*>(Vp + (size_t)d * N_ + i0 + iw);
                float h0 = bf16hi(f.x), h1 = bf16hi(f.y), h2 = bf16hi(f.z), h3 = bf16hi(f.w);
                int w = d * SWV + lane * 2;
                Vhi[w]     = packbf(h0, h1);
                Vhi[w + 1] = packbf(h2, h3);
                Vlo[w]     = packbf(f.x - h0, f.y - h1);
                Vlo[w + 1] = packbf(f.z - h2, f.w - h3);
            }
        }
        __syncthreads();

        // ================= Phase B: O += V_tile @ attn (K=128) ==============
#pragma unroll
        for (int ks = 0; ks < 8; ++ks) {
            const int ko = ks * 8;
            uint32_t bhi[4][2], blo[4][2];
#pragma unroll
            for (int nt = 0; nt < 4; ++nt) {
                int col = (wn * 32 + nt * 8 + g) * SWP;
                bhi[nt][0] = Pahi[col + ko + cc];
                bhi[nt][1] = Pahi[col + ko + 4 + cc];
                blo[nt][0] = Palo[col + ko + cc];
                blo[nt][1] = Palo[col + ko + 4 + cc];
            }
#pragma unroll
            for (int mt = 0; mt < 2; ++mt) {
                int r0 = (wm * 32 + mt * 16 + g) * SWV;
                int r8 = r0 + 8 * SWV;
                uint32_t ahi[4] = { Vhi[r0 + ko + cc], Vhi[r8 + ko + cc],
                                    Vhi[r0 + ko + 4 + cc], Vhi[r8 + ko + 4 + cc] };
                uint32_t alo[4] = { Vlo[r0 + ko + cc], Vlo[r8 + ko + cc],
                                    Vlo[r0 + ko + 4 + cc], Vlo[r8 + ko + 4 + cc] };
#pragma unroll
                for (int nt = 0; nt < 4; ++nt) {
                    mma16816(oacc[mt][nt], ahi, bhi[nt]);
                    mma16816(oacc[mt][nt], ahi, blo[nt]);
                    mma16816(oacc[mt][nt], alo, bhi[nt]);
                }
            }
        }
        __syncthreads();
    }

    // ---- write O tile [64 d][128 j] ----
#pragma unroll
    for (int mt = 0; mt < 2; ++mt)
#pragma unroll
        for (int nt = 0; nt < 4; ++nt) {
            int row = wm * 32 + mt * 16 + g;
            int col = wn * 32 + nt * 8 + 2 * cc;
            float2 v;
            v.x = oacc[mt][nt][0]; v.y = oacc[mt][nt][1];
            *reinterpret_cast<float2*>(Op + (size_t)row * N_ + col) = v;
            v.x = oacc[mt][nt][2]; v.y = oacc[mt][nt][3];
            *reinterpret_cast<float2*>(Op + (size_t)(row + 8) * N_ + col) = v;
        }
}

// ---------------------------------------------------------------------------
// Launch
// ---------------------------------------------------------------------------
extern "C" void kernel_launch(void* const* d_in, const int* in_sizes, int n_in,
                              void* d_out, int out_size)
{
    const float* x  = (const float*)d_in[0];
    const float* Wk = (const float*)d_in[1];
    const float* Wq = (const float*)d_in[2];
    const float* Wv = (const float*)d_in[3];
    const float* Wr = (const float*)d_in[4];
    const float* br = (const float*)d_in[5];
    float* out = (float*)d_out;

    float *gA, *gP, *gv, *go2;
    cudaGetSymbolAddress((void**)&gA,  g_A);
    cudaGetSymbolAddress((void**)&gP,  g_P);
    cudaGetSymbolAddress((void**)&gv,  g_v);
    cudaGetSymbolAddress((void**)&go2, g_o2);

    dim3 blk(256);

    // A[b,h] = x_b (256x1024) @ Wq_h (1024x256)
    mgemm_kernel<<<dim3(C_ / 128, C_ / 128, B_ * HEADS), blk>>>(
        x, Wq, gA, nullptr,
        C_, N_, C_, 3,
        (long long)C_ * N_, 0,
        0, (long long)DK * C_,
        (long long)HEADS * C_ * C_, (long long)C_ * C_);

    // P[b,h] = Wk_h (1024x256) @ A[b,h] (256x256)
    mgemm_kernel<<<dim3(C_ / 128, DK / 128, B_ * HEADS), blk>>>(
        Wk, gA, gP, nullptr,
        DK, C_, C_, 3,
        0, (long long)DK * C_,
        (long long)HEADS * C_ * C_, (long long)C_ * C_,
        (long long)HEADS * DK * C_, (long long)DK * C_);

    // v = Wv @ x_b : [B][512][1024]
    mgemm_kernel<<<dim3(N_ / 128, VC / 128, B_), blk>>>(
        Wv, x, gv, nullptr,
        VC, C_, N_, 0,
        0, 0,
        (long long)C_ * N_, 0,
        (long long)VC * N_, 0);

    // fused scores(K=256) -> chunked softmax -> V @ attn
    const int smem_words = 4 * 128 * SW + 128 * 132 + 2 * 128 * SWP + 2 * 64 * SWV;
    const int smem_bytes = smem_words * 4;
    cudaFuncSetAttribute(attn_kernel, cudaFuncAttributeMaxDynamicSharedMemorySize, smem_bytes);
    attn_kernel<<<dim3(NCHUNK, HEADS, B_), blk, smem_bytes>>>(x);

    // y = Wr @ o2 + br : [B][256][1024]
    mgemm_kernel<<<dim3(N_ / 128, C_ / 128, B_), blk>>>(
        Wr, go2, out, br,
        C_, VC, N_, 0,
        0, 0,
        (long long)VC * N_, 0,
        (long long)C_ * N_, 0);
}

// round 5
// speedup vs baseline: 2.0482x; 1.0110x over previous
#include <cuda_runtime.h>
#include <cuda_bf16.h>
#include <cstdint>

// Problem constants (fixed shapes from setup_inputs)
static constexpr int B_    = 8;
static constexpr int C_    = 256;
static constexpr int N_    = 1024;   // T*H*W
static constexpr int HEADS = 8;
static constexpr int DK    = 1024;   // KC / heads
static constexpr int DV    = 64;     // VC / heads
static constexpr int KC    = 8192;
static constexpr int VC    = 512;
static constexpr int CHUNKSZ = 128;
static constexpr int NCHUNK  = 8;

// Device scratch (no cudaMalloc allowed)
__device__ float g_A [(size_t)B_ * HEADS * C_ * C_];      // [b,h][256][256] fp32
__device__ float g_o2[(size_t)B_ * VC * N_];              // [b][512][1024] fp32
__device__ __nv_bfloat16 g_Phi[(size_t)B_ * HEADS * DK * C_];  // P split hi
__device__ __nv_bfloat16 g_Plo[(size_t)B_ * HEADS * DK * C_];  // P split lo
__device__ __nv_bfloat16 g_Vhi[(size_t)B_ * VC * N_];
__device__ __nv_bfloat16 g_Vlo[(size_t)B_ * VC * N_];
__device__ __nv_bfloat16 g_Xhi[(size_t)B_ * N_ * C_];     // x^T split [b][j][c]
__device__ __nv_bfloat16 g_Xlo[(size_t)B_ * N_ * C_];

// ---------------------------------------------------------------------------
// Helpers
// ---------------------------------------------------------------------------
__device__ __forceinline__ float bf16hi(float f)
{
    return __bfloat162float(__float2bfloat16(f));
}

// pack two floats (rounded to bf16) into one u32: first arg -> low half
__device__ __forceinline__ uint32_t packbf(float lo_el, float hi_el)
{
    uint32_t r;
    asm("cvt.rn.bf16x2.f32 %0, %1, %2;" : "=r"(r) : "f"(hi_el), "f"(lo_el));
    return r;
}

__device__ __forceinline__ void mma16816(float* d, const uint32_t* a, const uint32_t* b)
{
    asm volatile(
        "mma.sync.aligned.m16n8k16.row.col.f32.bf16.bf16.f32 "
        "{%0,%1,%2,%3}, {%4,%5,%6,%7}, {%8,%9}, {%0,%1,%2,%3};"
        : "+f"(d[0]), "+f"(d[1]), "+f"(d[2]), "+f"(d[3])
        : "r"(a[0]), "r"(a[1]), "r"(a[2]), "r"(a[3]), "r"(b[0]), "r"(b[1]));
}

__device__ __forceinline__ uint32_t smem_u32(const void* p)
{
    uint32_t a;
    asm("{ .reg .u64 t; cvta.to.shared.u64 t, %1; cvt.u32.u64 %0, t; }"
        : "=r"(a) : "l"(p));
    return a;
}

__device__ __forceinline__ void cp16(uint32_t dst, const void* src)
{
    asm volatile("cp.async.cg.shared.global [%0], [%1], 16;"
                 :: "r"(dst), "l"(src));
}
#define CP_COMMIT() asm volatile("cp.async.commit_group;" ::: "memory")

// smem strides (u32 words)
static constexpr int SW  = 20;  // staging tile row: 16 payload words + 4 pad (80B, 16B-aligned)
static constexpr int SWP = 69;  // attn tile row: 64 payload + 5 pad
static constexpr int SWV = 68;  // V tile row: 64 payload + 4 pad (272B, 16B-aligned)

// attn smem layout (u32 word offsets)
static constexpr int OFF_BUF   = 0;       // 2 x (Phi,Plo,Xhi,Xlo) each 128*SW
static constexpr int BUF_WORDS = 4 * 128 * SW;           // 10240 per buffer
static constexpr int OFF_REG   = 2 * BUF_WORDS;          // 20480: Sa (fp32) U Pa(hi/lo)
static constexpr int REG_WORDS = 2 * 128 * SWP;          // 17664 (Sa needs 16896)
static constexpr int OFF_V     = OFF_REG + REG_WORDS;    // 38144
static constexpr int V_WORDS   = 2 * 64 * SWV;           // 8704
static constexpr int SMEM_WORDS_ATTN = OFF_V + V_WORDS;  // 46848 words = 187392 B

// ---------------------------------------------------------------------------
// Generic batched GEMM via bf16x3-split tensor-core MMA, fp32 in.
// Output: fp32 (+bias) if OutHi==nullptr, else split bf16 hi/lo (no fp32 out).
// CTA tile 128x128, K-stage 32, 256 threads = 8 warps (2m x 4n).
// ---------------------------------------------------------------------------
__global__ __launch_bounds__(256, 2)
void mgemm_kernel(const float* __restrict__ W, const float* __restrict__ X,
                  float* __restrict__ Out, const float* __restrict__ bias,
                  __nv_bfloat16* __restrict__ OutHi, __nv_bfloat16* __restrict__ OutLo,
                  int M, int K, int N, int hbits,
                  long long sWb, long long sWh,
                  long long sXb, long long sXh,
                  long long sOb, long long sOh)
{
    __shared__ uint32_t Whi[128 * SW], Wlo[128 * SW];
    __shared__ uint32_t Xhi[128 * SW], Xlo[128 * SW];

    const int z = blockIdx.z;
    const int zb = z >> hbits;
    const int zh = z & ((1 << hbits) - 1);
    const float* Wp = W + (size_t)zb * sWb + (size_t)zh * sWh;
    const float* Xp = X + (size_t)zb * sXb + (size_t)zh * sXh;
    const size_t obase = (size_t)zb * sOb + (size_t)zh * sOh;

    const int m0 = blockIdx.y * 128;
    const int n0 = blockIdx.x * 128;
    const int tid  = threadIdx.x;
    const int lane = tid & 31;
    const int wid  = tid >> 5;
    const int wm = wid >> 2;
    const int wn = wid & 3;
    const int g  = lane >> 2;
    const int cc = lane & 3;

    float acc[4][4][4];
#pragma unroll
    for (int mt = 0; mt < 4; ++mt)
#pragma unroll
        for (int nt = 0; nt < 4; ++nt)
#pragma unroll
            for (int e = 0; e < 4; ++e) acc[mt][nt][e] = 0.f;

    for (int k0 = 0; k0 < K; k0 += 32) {
        // ---- stage W tile [128 m][32 k] -> hi/lo bf16 ----
        {
            const int r = tid >> 1;
            const int half = tid & 1;
            const float* src = Wp + (size_t)(m0 + r) * K + k0 + half * 16;
#pragma unroll
            for (int q = 0; q < 4; ++q) {
                float4 f = *reinterpret_cast<const float4*>(src + q * 4);
                float h0 = bf16hi(f.x), h1 = bf16hi(f.y), h2 = bf16hi(f.z), h3 = bf16hi(f.w);
                int w = r * SW + half * 8 + q * 2;
                Whi[w]     = packbf(h0, h1);
                Whi[w + 1] = packbf(h2, h3);
                Wlo[w]     = packbf(f.x - h0, f.y - h1);
                Wlo[w + 1] = packbf(f.z - h2, f.w - h3);
            }
        }
        // ---- stage X tile [32 k][128 n] -> transposed [n][k] hi/lo ----
        {
            const int n = tid & 127;
            const int kh = tid >> 7;
            const float* src = Xp + (size_t)(k0 + kh * 16) * N + n0 + n;
#pragma unroll
            for (int kq = 0; kq < 8; ++kq) {
                float f0 = src[(size_t)(2 * kq) * N];
                float f1 = src[(size_t)(2 * kq + 1) * N];
                float h0 = bf16hi(f0), h1 = bf16hi(f1);
                int w = n * SW + kh * 8 + kq;
                Xhi[w] = packbf(h0, h1);
                Xlo[w] = packbf(f0 - h0, f1 - h1);
            }
        }
        __syncthreads();

#pragma unroll
        for (int h16 = 0; h16 < 2; ++h16) {
            const int ko = h16 * 8;
            uint32_t bhi[4][2], blo[4][2];
#pragma unroll
            for (int nt = 0; nt < 4; ++nt) {
                int col = (wn * 32 + nt * 8 + g) * SW;
                bhi[nt][0] = Xhi[col + ko + cc];
                bhi[nt][1] = Xhi[col + ko + 4 + cc];
                blo[nt][0] = Xlo[col + ko + cc];
                blo[nt][1] = Xlo[col + ko + 4 + cc];
            }
#pragma unroll
            for (int mt = 0; mt < 4; ++mt) {
                int r0 = (wm * 64 + mt * 16 + g) * SW;
                int r8 = r0 + 8 * SW;
                uint32_t ahi[4] = { Whi[r0 + ko + cc], Whi[r8 + ko + cc],
                                    Whi[r0 + ko + 4 + cc], Whi[r8 + ko + 4 + cc] };
                uint32_t alo[4] = { Wlo[r0 + ko + cc], Wlo[r8 + ko + cc],
                                    Wlo[r0 + ko + 4 + cc], Wlo[r8 + ko + 4 + cc] };
#pragma unroll
                for (int nt = 0; nt < 4; ++nt) {
                    mma16816(acc[mt][nt], ahi, bhi[nt]);
                    mma16816(acc[mt][nt], ahi, blo[nt]);
                    mma16816(acc[mt][nt], alo, bhi[nt]);
                }
            }
        }
        __syncthreads();
    }

    // ---- epilogue ----
    if (OutHi == nullptr) {
        float* Op = Out + obase;
#pragma unroll
        for (int mt = 0; mt < 4; ++mt)
#pragma unroll
            for (int nt = 0; nt < 4; ++nt) {
                int row = m0 + wm * 64 + mt * 16 + g;
                int col = n0 + wn * 32 + nt * 8 + 2 * cc;
                float b0 = bias ? bias[row] : 0.f;
                float b1 = bias ? bias[row + 8] : 0.f;
                float2 v;
                v.x = acc[mt][nt][0] + b0; v.y = acc[mt][nt][1] + b0;
                *reinterpret_cast<float2*>(Op + (size_t)row * N + col) = v;
                v.x = acc[mt][nt][2] + b1; v.y = acc[mt][nt][3] + b1;
                *reinterpret_cast<float2*>(Op + (size_t)(row + 8) * N + col) = v;
            }
    } else {
        uint32_t* Hw = reinterpret_cast<uint32_t*>(OutHi + obase);
        uint32_t* Lw = reinterpret_cast<uint32_t*>(OutLo + obase);
#pragma unroll
        for (int mt = 0; mt < 4; ++mt)
#pragma unroll
            for (int nt = 0; nt < 4; ++nt) {
                int row = m0 + wm * 64 + mt * 16 + g;
                int col = n0 + wn * 32 + nt * 8 + 2 * cc;
                float v0 = acc[mt][nt][0], v1 = acc[mt][nt][1];
                float h0 = bf16hi(v0), h1 = bf16hi(v1);
                Hw[((size_t)row * N + col) >> 1] = packbf(h0, h1);
                Lw[((size_t)row * N + col) >> 1] = packbf(v0 - h0, v1 - h1);
                v0 = acc[mt][nt][2]; v1 = acc[mt][nt][3];
                h0 = bf16hi(v0); h1 = bf16hi(v1);
                Hw[((size_t)(row + 8) * N + col) >> 1] = packbf(h0, h1);
                Lw[((size_t)(row + 8) * N + col) >> 1] = packbf(v0 - h0, v1 - h1);
            }
    }
}

// ---------------------------------------------------------------------------
// x transpose + split: x [b][256 c][1024 j] fp32 -> g_Xhi/g_Xlo [b][j][c] bf16
// ---------------------------------------------------------------------------
__global__ __launch_bounds__(256)
void xsplit_kernel(const float* __restrict__ x)
{
    __shared__ float tile[32][33];
    const int b  = blockIdx.z;
    const int c0 = blockIdx.y * 32;
    const int j0 = blockIdx.x * 32;
    const int txx = threadIdx.x & 31;
    const int tyy = threadIdx.x >> 5;   // 0..7

#pragma unroll
    for (int i = 0; i < 4; ++i) {
        int c = c0 + tyy + i * 8;
        tile[tyy + i * 8][txx] = x[((size_t)b * C_ + c) * N_ + j0 + txx];
    }
    __syncthreads();
#pragma unroll
    for (int i = 0; i < 4; ++i) {
        int j = j0 + tyy + i * 8;
        float f = tile[txx][tyy + i * 8];
        float h = bf16hi(f);
        size_t o = ((size_t)b * N_ + j) * C_ + c0 + txx;
        g_Xhi[o] = __float2bfloat16(f);
        g_Xlo[o] = __float2bfloat16(f - h);
    }
}

// ---------------------------------------------------------------------------
// Fused attention kernel, cp.async pipelined, all-bf16 pre-split inputs.
// One CTA per (chunk, head, batch). 8 i-tiles of 128 dk-rows:
//   Phase A: S = P_tile @ x_chunk (K=256, double-buffered cp.async)
//   softmax over 128 chunk columns
//   Phase B: O += V_tile @ attn
// ---------------------------------------------------------------------------
__global__ __launch_bounds__(256, 1)
void attn_kernel()
{
    extern __shared__ __align__(16) char smraw[];
    uint32_t* SMw = reinterpret_cast<uint32_t*>(smraw);
    const uint32_t smb = smem_u32(smraw);

    const int chunk = blockIdx.x;
    const int h     = blockIdx.y;
    const int b     = blockIdx.z;

    const size_t pRowBase = (size_t)(b * HEADS + h) * DK;   // P rows (i)
    const size_t xRowBase = (size_t)b * N_ + chunk * CHUNKSZ; // x^T rows (j)
    const size_t vRowBase = (size_t)b * VC + h * DV;          // V rows (d)
    float* Op = g_o2 + vRowBase * N_ + chunk * CHUNKSZ;

    const int tid  = threadIdx.x;
    const int lane = tid & 31;
    const int wid  = tid >> 5;
    const int wm = wid >> 2;
    const int wn = wid & 3;
    const int g  = lane >> 2;
    const int cc = lane & 3;
    const int tx = tid & 15;
    const int ty = tid >> 4;

    // staging thread coords
    const int sr   = tid & 127;        // row 0..127
    const int ssel = tid >> 7;         // 0 = hi, 1 = lo
    const int vd   = tid & 63;         // V row
    const int vrest = tid >> 6;        // 0..3
    const int vsel = vrest & 1;
    const int vhalf = vrest >> 1;

    const float scale = 0.03125f;  // 1/sqrt(1024)

    float oacc[2][4][4];
#pragma unroll
    for (int mt = 0; mt < 2; ++mt)
#pragma unroll
        for (int nt = 0; nt < 4; ++nt)
#pragma unroll
            for (int e = 0; e < 4; ++e) oacc[mt][nt][e] = 0.f;

    float* Sa = reinterpret_cast<float*>(SMw + OFF_REG);        // [128][132]
    uint32_t* Pahi = SMw + OFF_REG;                             // alias of Sa
    uint32_t* Palo = SMw + OFF_REG + 128 * SWP;
    uint32_t* Vhi  = SMw + OFF_V;
    uint32_t* Vlo  = SMw + OFF_V + 64 * SWV;

    for (int it = 0; it < 8; ++it) {
        const int i0 = it * 128;

        // ---- G0: V tile + PX buffer 0 ----
        {
            const __nv_bfloat16* srcV = (vsel ? g_Vlo : g_Vhi)
                + ((size_t)(vRowBase + vd) * N_ + i0 + vhalf * 64);
            uint32_t dV = smb + (OFF_V + vsel * 64 * SWV + vd * SWV) * 4 + vhalf * 128;
#pragma unroll
            for (int q = 0; q < 8; ++q)
                cp16(dV + q * 16, srcV + q * 8);
        }
        {
            const __nv_bfloat16* srcP = (ssel ? g_Plo : g_Phi)
                + ((pRowBase + i0 + sr) * C_ + 0);
            const __nv_bfloat16* srcX = (ssel ? g_Xlo : g_Xhi)
                + ((xRowBase + sr) * C_ + 0);
            uint32_t dP = smb + (ssel * 2560 + sr * SW) * 4;
            uint32_t dX = smb + (5120 + ssel * 2560 + sr * SW) * 4;
#pragma unroll
            for (int q = 0; q < 4; ++q) {
                cp16(dP + q * 16, srcP + q * 8);
                cp16(dX + q * 16, srcX + q * 8);
            }
        }
        CP_COMMIT();
        // ---- G1: PX buffer 1 (m0 = 32) ----
        {
            const __nv_bfloat16* srcP = (ssel ? g_Plo : g_Phi)
                + ((pRowBase + i0 + sr) * C_ + 32);
            const __nv_bfloat16* srcX = (ssel ? g_Xlo : g_Xhi)
                + ((xRowBase + sr) * C_ + 32);
            uint32_t dP = smb + (BUF_WORDS + ssel * 2560 + sr * SW) * 4;
            uint32_t dX = smb + (BUF_WORDS + 5120 + ssel * 2560 + sr * SW) * 4;
#pragma unroll
            for (int q = 0; q < 4; ++q) {
                cp16(dP + q * 16, srcP + q * 8);
                cp16(dX + q * 16, srcX + q * 8);
            }
        }
        CP_COMMIT();

        // ================= Phase A =================
        float sacc[4][4][4];
#pragma unroll
        for (int mt = 0; mt < 4; ++mt)
#pragma unroll
            for (int nt = 0; nt < 4; ++nt)
#pragma unroll
                for (int e = 0; e < 4; ++e) sacc[mt][nt][e] = 0.f;

        for (int s = 0; s < 8; ++s) {
            if (s < 7) asm volatile("cp.async.wait_group 1;" ::: "memory");
            else       asm volatile("cp.async.wait_group 0;" ::: "memory");
            __syncthreads();

            const uint32_t* bPhi = SMw + (s & 1) * BUF_WORDS;
            const uint32_t* bPlo = bPhi + 2560;
            const uint32_t* bXhi = bPhi + 5120;
            const uint32_t* bXlo = bPhi + 7680;

#pragma unroll
            for (int h16 = 0; h16 < 2; ++h16) {
                const int ko = h16 * 8;
                uint32_t bhi[4][2], blo[4][2];
#pragma unroll
                for (int nt = 0; nt < 4; ++nt) {
                    int col = (wn * 32 + nt * 8 + g) * SW;
                    bhi[nt][0] = bXhi[col + ko + cc];
                    bhi[nt][1] = bXhi[col + ko + 4 + cc];
                    blo[nt][0] = bXlo[col + ko + cc];
                    blo[nt][1] = bXlo[col + ko + 4 + cc];
                }
#pragma unroll
                for (int mt = 0; mt < 4; ++mt) {
                    int r0 = (wm * 64 + mt * 16 + g) * SW;
                    int r8 = r0 + 8 * SW;
                    uint32_t ahi[4] = { bPhi[r0 + ko + cc], bPhi[r8 + ko + cc],
                                        bPhi[r0 + ko + 4 + cc], bPhi[r8 + ko + 4 + cc] };
                    uint32_t alo[4] = { bPlo[r0 + ko + cc], bPlo[r8 + ko + cc],
                                        bPlo[r0 + ko + 4 + cc], bPlo[r8 + ko + 4 + cc] };
#pragma unroll
                    for (int nt = 0; nt < 4; ++nt) {
                        mma16816(sacc[mt][nt], ahi, bhi[nt]);
                        mma16816(sacc[mt][nt], ahi, blo[nt]);
                        mma16816(sacc[mt][nt], alo, bhi[nt]);
                    }
                }
            }
            __syncthreads();   // everyone done reading buf[s&1]

            if (s + 2 < 8) {
                const int m0 = (s + 2) * 32;
                const __nv_bfloat16* srcP = (ssel ? g_Plo : g_Phi)
                    + ((pRowBase + i0 + sr) * C_ + m0);
                const __nv_bfloat16* srcX = (ssel ? g_Xlo : g_Xhi)
                    + ((xRowBase + sr) * C_ + m0);
                uint32_t dP = smb + ((s & 1) * BUF_WORDS + ssel * 2560 + sr * SW) * 4;
                uint32_t dX = smb + ((s & 1) * BUF_WORDS + 5120 + ssel * 2560 + sr * SW) * 4;
#pragma unroll
                for (int q = 0; q < 4; ++q) {
                    cp16(dP + q * 16, srcP + q * 8);
                    cp16(dX + q * 16, srcX + q * 8);
                }
                CP_COMMIT();
            }
        }

        // ---- write S fragments to Sa (fp32) ----
#pragma unroll
        for (int mt = 0; mt < 4; ++mt)
#pragma unroll
            for (int nt = 0; nt < 4; ++nt) {
                int row = wm * 64 + mt * 16 + g;
                int col = wn * 32 + nt * 8 + 2 * cc;
                float2 v;
                v.x = sacc[mt][nt][0]; v.y = sacc[mt][nt][1];
                *reinterpret_cast<float2*>(&Sa[row * 132 + col]) = v;
                v.x = sacc[mt][nt][2]; v.y = sacc[mt][nt][3];
                *reinterpret_cast<float2*>(&Sa[(row + 8) * 132 + col]) = v;
            }
        __syncthreads();

        // ================= Softmax =================
        {
            float P_[8][8];
#pragma unroll
            for (int r = 0; r < 8; ++r) {
                float4 a4 = *reinterpret_cast<const float4*>(&Sa[(ty * 8 + r) * 132 + tx * 8]);
                float4 b4 = *reinterpret_cast<const float4*>(&Sa[(ty * 8 + r) * 132 + tx * 8 + 4]);
                P_[r][0] = a4.x; P_[r][1] = a4.y; P_[r][2] = a4.z; P_[r][3] = a4.w;
                P_[r][4] = b4.x; P_[r][5] = b4.y; P_[r][6] = b4.z; P_[r][7] = b4.w;
            }
#pragma unroll
            for (int r = 0; r < 8; ++r) {
                float mx = -1e30f;
#pragma unroll
                for (int c = 0; c < 8; ++c) { P_[r][c] *= scale; mx = fmaxf(mx, P_[r][c]); }
#pragma unroll
                for (int off = 8; off >= 1; off >>= 1)
                    mx = fmaxf(mx, __shfl_xor_sync(0xffffffffu, mx, off));
                float sum = 0.f;
#pragma unroll
                for (int c = 0; c < 8; ++c) { P_[r][c] = __expf(P_[r][c] - mx); sum += P_[r][c]; }
#pragma unroll
                for (int off = 8; off >= 1; off >>= 1)
                    sum += __shfl_xor_sync(0xffffffffu, sum, off);
                float inv = 1.0f / sum;
#pragma unroll
                for (int c = 0; c < 8; ++c) P_[r][c] *= inv;
            }
            __syncthreads();   // Sa reads done before Pa overwrite (aliased)

            // write attn transposed [j][i] as bf16 hi/lo (i-pairs packed)
#pragma unroll
            for (int c = 0; c < 8; ++c) {
                int base = (tx * 8 + c) * SWP + ty * 4;
#pragma unroll
                for (int s = 0; s < 4; ++s) {
                    float p0 = P_[2 * s][c], p1 = P_[2 * s + 1][c];
                    float h0 = bf16hi(p0), h1 = bf16hi(p1);
                    Pahi[base + s] = packbf(h0, h1);
                    Palo[base + s] = packbf(p0 - h0, p1 - h1);
                }
            }
        }
        __syncthreads();

        // ================= Phase B: O += V_tile @ attn (K=128) ==============
#pragma unroll
        for (int ks = 0; ks < 8; ++ks) {
            const int ko = ks * 8;
            uint32_t bhi[4][2], blo[4][2];
#pragma unroll
            for (int nt = 0; nt < 4; ++nt) {
                int col = (wn * 32 + nt * 8 + g) * SWP;
                bhi[nt][0] = Pahi[col + ko + cc];
                bhi[nt][1] = Pahi[col + ko + 4 + cc];
                blo[nt][0] = Palo[col + ko + cc];
                blo[nt][1] = Palo[col + ko + 4 + cc];
            }
#pragma unroll
            for (int mt = 0; mt < 2; ++mt) {
                int r0 = (wm * 32 + mt * 16 + g) * SWV;
                int r8 = r0 + 8 * SWV;
                uint32_t ahi[4] = { Vhi[r0 + ko + cc], Vhi[r8 + ko + cc],
                                    Vhi[r0 + ko + 4 + cc], Vhi[r8 + ko + 4 + cc] };
                uint32_t alo[4] = { Vlo[r0 + ko + cc], Vlo[r8 + ko + cc],
                                    Vlo[r0 + ko + 4 + cc], Vlo[r8 + ko + 4 + cc] };
#pragma unroll
                for (int nt = 0; nt < 4; ++nt) {
                    mma16816(oacc[mt][nt], ahi, bhi[nt]);
                    mma16816(oacc[mt][nt], ahi, blo[nt]);
                    mma16816(oacc[mt][nt], alo, bhi[nt]);
                }
            }
        }
        __syncthreads();   // done with V + Pa before next i-tile overwrites
    }

    // ---- write O tile [64 d][128 j] ----
#pragma unroll
    for (int mt = 0; mt < 2; ++mt)
#pragma unroll
        for (int nt = 0; nt < 4; ++nt) {
            int row = wm * 32 + mt * 16 + g;
            int col = wn * 32 + nt * 8 + 2 * cc;
            float2 v;
            v.x = oacc[mt][nt][0]; v.y = oacc[mt][nt][1];
            *reinterpret_cast<float2*>(Op + (size_t)row * N_ + col) = v;
            v.x = oacc[mt][nt][2]; v.y = oacc[mt][nt][3];
            *reinterpret_cast<float2*>(Op + (size_t)(row + 8) * N_ + col) = v;
        }
}

// ---------------------------------------------------------------------------
// Launch
// ---------------------------------------------------------------------------
extern "C" void kernel_launch(void* const* d_in, const int* in_sizes, int n_in,
                              void* d_out, int out_size)
{
    const float* x  = (const float*)d_in[0];
    const float* Wk = (const float*)d_in[1];
    const float* Wq = (const float*)d_in[2];
    const float* Wv = (const float*)d_in[3];
    const float* Wr = (const float*)d_in[4];
    const float* br = (const float*)d_in[5];
    float* out = (float*)d_out;

    float *gA, *go2;
    __nv_bfloat16 *gPhi, *gPlo, *gVhi, *gVlo;
    cudaGetSymbolAddress((void**)&gA,   g_A);
    cudaGetSymbolAddress((void**)&go2,  g_o2);
    cudaGetSymbolAddress((void**)&gPhi, g_Phi);
    cudaGetSymbolAddress((void**)&gPlo, g_Plo);
    cudaGetSymbolAddress((void**)&gVhi, g_Vhi);
    cudaGetSymbolAddress((void**)&gVlo, g_Vlo);

    dim3 blk(256);

    // A[b,h] = x_b (256x1024) @ Wq_h (1024x256)  -> fp32
    mgemm_kernel<<<dim3(C_ / 128, C_ / 128, B_ * HEADS), blk>>>(
        x, Wq, gA, nullptr, nullptr, nullptr,
        C_, N_, C_, 3,
        (long long)C_ * N_, 0,
        0, (long long)DK * C_,
        (long long)HEADS * C_ * C_, (long long)C_ * C_);

    // P[b,h] = Wk_h (1024x256) @ A[b,h] (256x256) -> split bf16
    mgemm_kernel<<<dim3(C_ / 128, DK / 128, B_ * HEADS), blk>>>(
        Wk, gA, nullptr, nullptr, gPhi, gPlo,
        DK, C_, C_, 3,
        0, (long long)DK * C_,
        (long long)HEADS * C_ * C_, (long long)C_ * C_,
        (long long)HEADS * DK * C_, (long long)DK * C_);

    // v = Wv @ x_b : [B][512][1024] -> split bf16
    mgemm_kernel<<<dim3(N_ / 128, VC / 128, B_), blk>>>(
        Wv, x, nullptr, nullptr, gVhi, gVlo,
        VC, C_, N_, 0,
        0, 0,
        (long long)C_ * N_, 0,
        (long long)VC * N_, 0);

    // x^T split
    xsplit_kernel<<<dim3(N_ / 32, C_ / 32, B_), blk>>>(x);

    // fused attention
    const int smem_bytes = SMEM_WORDS_ATTN * 4;
    cudaFuncSetAttribute(attn_kernel, cudaFuncAttributeMaxDynamicSharedMemorySize, smem_bytes);
    attn_kernel<<<dim3(NCHUNK, HEADS, B_), blk, smem_bytes>>>();

    // y = Wr @ o2 + br : [B][256][1024]
    mgemm_kernel<<<dim3(N_ / 128, C_ / 128, B_), blk>>>(
        Wr, go2, out, br, nullptr, nullptr,
        C_, VC, N_, 0,
        0, 0,
        (long long)VC * N_, 0,
        (long long)C_ * N_, 0);
}